// round 16
// baseline (speedup 1.0000x reference)
#include <cuda_runtime.h>
#include <cuda_bf16.h>
#include <math.h>
#include <stdint.h>

// Problem constants (fixed by the dataset)
#define BB   32
#define NSEQ 1024
#define CC   768
#define HH   12
#define DD   64
#define OUTF 2496            // 3C + 3D
#define XCATC 832            // C + D
#define MROWS (BB*NSEQ)      // 32768

#define ESC_CONST (-(1.0f/1024.0f)*(1.0f/3.0f))

// GEMM tiling: 128(M) x 256(N) CTA tile, 8 warps of 64x64, KC=32, 2 stages
#define MT 128
#define NTG 256
#define KC 32
#define A_BYTES (128 * 32 * 4)              // 16384
#define GSTAGE_BYTES ((128 + 256) * 32 * 4) // 49152 per stage
#define GSMEM_BYTES (2 * GSTAGE_BYTES)      // 98304

// Scratch (device globals -> no allocation)
__device__ float g_qkv[(size_t)MROWS * OUTF];     // [32768, 2496]
__device__ float g_xcat[(size_t)MROWS * XCATC];   // [32768, 832]
__device__ float g_Wt1[(size_t)2560 * CC];        // W_qkv^T padded to 2560 rows
__device__ float g_Wt2[(size_t)CC * XCATC];       // proj_W^T [768, 832]
__device__ float g_w1u[(size_t)BB * HH * 4352];   // updated W1 [e][d], LD=68
__device__ float g_w2u[(size_t)BB * HH * 4352];   // updated W2 [e][d], LD=68

__device__ __forceinline__ uint32_t smem_u32(const void* p) {
    uint32_t a;
    asm("{ .reg .u64 t; cvta.to.shared.u64 t, %1; cvt.u32.u64 %0, t; }" : "=r"(a) : "l"(p));
    return a;
}
__device__ __forceinline__ void cp16(uint32_t dst, const void* src) {
    asm volatile("cp.async.cg.shared.global [%0], [%1], 16;" :: "r"(dst), "l"(src));
}
#define CP_COMMIT() asm volatile("cp.async.commit_group;" ::: "memory")
#define CP_WAIT1()  asm volatile("cp.async.wait_group 1;" ::: "memory")
#define CP_WAIT0()  asm volatile("cp.async.wait_group 0;" ::: "memory")

__device__ __forceinline__ uint32_t f2tf32(float f) {
    uint32_t r;
    asm("cvt.rna.tf32.f32 %0, %1;" : "=r"(r) : "f"(f));
    return r;
}

#define MMA_TF32(d, a0, a1, a2, a3, b0, b1) \
    asm volatile( \
        "mma.sync.aligned.m16n8k8.row.col.f32.tf32.tf32.f32 " \
        "{%0,%1,%2,%3}, {%4,%5,%6,%7}, {%8,%9}, {%0,%1,%2,%3};" \
        : "+f"((d)[0]), "+f"((d)[1]), "+f"((d)[2]), "+f"((d)[3]) \
        : "r"(a0), "r"(a1), "r"(a2), "r"(a3), "r"(b0), "r"(b1))

// swizzled smem read (GEMM): row r (stride 32 floats), col c
__device__ __forceinline__ float ldsw(const float* s, int r, int c) {
    return s[r * 32 + ((((c >> 2) ^ (r & 7)) << 2) | (c & 3))];
}

// ---------------------------------------------------------------------------
// Transpose with row padding: out[n][k] = in[k][n]; zero rows n in [inC, outR)
// ---------------------------------------------------------------------------
__global__ void transpose_pad_kernel(const float* __restrict__ in, float* __restrict__ out,
                                     int inR, int inC, int outR)
{
    __shared__ float t[32][33];
    int kb = blockIdx.y * 32, nb = blockIdx.x * 32;
    int x = threadIdx.x, y = threadIdx.y;
    for (int i = y; i < 32; i += 8) {
        int k = kb + i, n = nb + x;
        t[i][x] = (k < inR && n < inC) ? in[(size_t)k * inC + n] : 0.f;
    }
    __syncthreads();
    for (int i = y; i < 32; i += 8) {
        int n = nb + i, k = kb + x;
        if (n < outR && k < inR) out[(size_t)n * inR + k] = t[x][i];
    }
}

// ---------------------------------------------------------------------------
// TF32 mma.sync GEMM, 128x256 CTA tile, 256 threads (8 warps, 64x64 each),
// 2-stage cp.async double buffer (fill t+1 overlaps compute t).
// C[M,Nn] = A[M,K] @ Bt[*,K]^T + bias[Nn]
// ---------------------------------------------------------------------------
__device__ __forceinline__ void fill_stage(uint32_t sbase,
    const float* __restrict__ A, const float* __restrict__ Bt,
    int m0, int n0, int K, int k0, int tid)
{
    const float* Ab = A + (size_t)m0 * K + k0;
#pragma unroll
    for (int i = 0; i < 4; i++) {          // 128 rows x 8 quads = 1024
        int idx = tid + i * 256;
        int r = idx >> 3, q = idx & 7;
        uint32_t off = (uint32_t)(r * 128 + ((q ^ (r & 7)) * 16));
        cp16(sbase + off, Ab + (size_t)r * K + q * 4);
    }
    const float* Bb = Bt + (size_t)n0 * K + k0;
#pragma unroll
    for (int i = 0; i < 8; i++) {          // 256 rows x 8 quads = 2048
        int idx = tid + i * 256;
        int r = idx >> 3, q = idx & 7;
        uint32_t off = (uint32_t)(r * 128 + ((q ^ (r & 7)) * 16));
        cp16(sbase + (uint32_t)A_BYTES + off, Bb + (size_t)r * K + q * 4);
    }
}

__global__ __launch_bounds__(256) void gemm_mma_kernel(
    const float* __restrict__ A, const float* __restrict__ Bt,
    const float* __restrict__ bias, float* __restrict__ C,
    int M, int Nn, int K)
{
    extern __shared__ float sm[];
    const uint32_t sb = smem_u32(sm);

    const int tid = threadIdx.x;
    const int wid = tid >> 5, lane = tid & 31;
    const int g = lane >> 2, tg = lane & 3;
    const int wm = (wid >> 2) * 64;       // 2 M halves
    const int wn = (wid & 3) * 64;        // 4 N quarters
    const int m0 = blockIdx.y * MT;
    const int n0 = blockIdx.x * NTG;
    const int nk = K / KC;

    float acc[4][8][4];
#pragma unroll
    for (int mi = 0; mi < 4; mi++)
#pragma unroll
        for (int nj = 0; nj < 8; nj++)
#pragma unroll
            for (int q = 0; q < 4; q++) acc[mi][nj][q] = 0.f;

    fill_stage(sb, A, Bt, m0, n0, K, 0, tid);
    CP_COMMIT();

    for (int kt = 0; kt < nk; kt++) {
        // issue fill(t+1) before waiting on fill(t) — overlaps compute(t)
        if (kt + 1 < nk)
            fill_stage(sb + (uint32_t)((kt + 1) & 1) * GSTAGE_BYTES,
                       A, Bt, m0, n0, K, (kt + 1) * KC, tid);
        CP_COMMIT();          // one group per iteration (may be empty)
        CP_WAIT1();           // fill(t) retired
        __syncthreads();

        const float* a_s = sm + (size_t)(kt & 1) * (GSTAGE_BYTES / 4);
        const float* b_s = a_s + A_BYTES / 4;
#pragma unroll
        for (int ks = 0; ks < 4; ks++) {
            const int kk = ks * 8;
            uint32_t a[4][4], b[8][2];
#pragma unroll
            for (int mi = 0; mi < 4; mi++) {
                const int row = wm + mi * 16;
                a[mi][0] = __float_as_uint(ldsw(a_s, row + g,     kk + tg));
                a[mi][1] = __float_as_uint(ldsw(a_s, row + g + 8, kk + tg));
                a[mi][2] = __float_as_uint(ldsw(a_s, row + g,     kk + tg + 4));
                a[mi][3] = __float_as_uint(ldsw(a_s, row + g + 8, kk + tg + 4));
            }
#pragma unroll
            for (int nj = 0; nj < 8; nj++) {
                const int col = wn + nj * 8;
                b[nj][0] = __float_as_uint(ldsw(b_s, col + g, kk + tg));
                b[nj][1] = __float_as_uint(ldsw(b_s, col + g, kk + tg + 4));
            }
#pragma unroll
            for (int mi = 0; mi < 4; mi++)
#pragma unroll
                for (int nj = 0; nj < 8; nj++)
                    MMA_TF32(acc[mi][nj], a[mi][0], a[mi][1], a[mi][2], a[mi][3],
                             b[nj][0], b[nj][1]);
        }
        __syncthreads();
    }

    // epilogue
#pragma unroll
    for (int nj = 0; nj < 8; nj++) {
        const int gc = n0 + wn + nj * 8 + tg * 2;
        if (gc >= Nn) continue;
        const float bx = bias[gc], by = bias[gc + 1];
#pragma unroll
        for (int mi = 0; mi < 4; mi++) {
            const int row = m0 + wm + mi * 16 + g;
            float2 s0 = make_float2(acc[mi][nj][0] + bx, acc[mi][nj][1] + by);
            float2 s1 = make_float2(acc[mi][nj][2] + bx, acc[mi][nj][3] + by);
            *(float2*)&C[(size_t)row * Nn + gc] = s0;
            *(float2*)&C[(size_t)(row + 8) * Nn + gc] = s1;
        }
    }
}

// ---------------------------------------------------------------------------
// SwiGLU gradient + weight update (phases A+B only), 512 threads.
// V tiles staged in smem via cp.async (coalesced).
// ---------------------------------------------------------------------------
#define LDS_W 68
#define SWT_F (128 * LDS_W)          // 8704 floats per 128-row tile
#define SW_W2 (64 * LDS_W)           // 4352
#define SW_EA (2 * 64 * LDS_W)       // 8704
#define SW_EG (SW_EA + SWT_F)
#define SW_KS (SW_EG + SWT_F)
#define SW_CS (SW_KS + 2 * SWT_F)
#define SW_V  (SW_CS + 128)          // V tile buffer (single, 8704 floats)
#define SW_TOT (SW_V + SWT_F)        // 52352 floats
#define SW_BYTES (SW_TOT * 4)        // 209408 bytes

__device__ __forceinline__ void sw_cp_tile(uint32_t dst, const float* src, int tid) {
#pragma unroll
    for (int i = 0; i < 4; i++) {
        int idx = tid + i * 512;
        int r = idx >> 4, c4 = (idx & 15) << 2;
        cp16(dst + (uint32_t)(r * LDS_W + c4) * 4u, src + (size_t)r * OUTF + c4);
    }
}

__global__ __launch_bounds__(512) void swiglu_grad_kernel(
    const float* __restrict__ w1, const float* __restrict__ w2)
{
    extern __shared__ float sw[];
    float* W1t = sw;
    float* W2t = sw + SW_W2;
    float* EA  = sw + SW_EA;
    float* EG  = sw + SW_EG;
    float* KS  = sw + SW_KS;
    float* CS  = sw + SW_CS;
    float* VS  = sw + SW_V;
    const uint32_t ks_addr0 = smem_u32(sw + SW_KS);
    const uint32_t vs_addr  = smem_u32(sw + SW_V);

    const int b = blockIdx.x / HH, h = blockIdx.x % HH;
    const int tid = threadIdx.x;
    const int wid = tid >> 5, lane = tid & 31;
    const int g = lane >> 2, tg = lane & 3;
    const int wm = (wid & 3) * 32;
    const int eh = (wid >> 2) * 16;
    const int w8 = wid & 7;
    const int ds = (w8 & 3) * 16;
    const int eh2 = (w8 >> 2) * 32;
    const int isW2 = wid >> 3;

    for (int i = tid; i < DD * DD; i += 512) {
        int d = i >> 6, e = i & 63;
        W1t[e * LDS_W + d] = __uint_as_float(f2tf32(w1[h * DD * DD + i]));
        W2t[e * LDS_W + d] = __uint_as_float(f2tf32(w2[h * DD * DD + i]));
    }
    if (tid < 128) CS[tid] = 0.f;

    float G[4][4];
#pragma unroll
    for (int nt = 0; nt < 4; nt++)
#pragma unroll
        for (int q = 0; q < 4; q++) G[nt][q] = 0.f;

    const size_t rowbase = (size_t)b * NSEQ;
    const float* kcol = g_qkv + rowbase * OUTF + CC + h * DD;
    const float* vcol = g_qkv + rowbase * OUTF + 2 * CC + h * DD;

    sw_cp_tile(ks_addr0, kcol, tid);
    CP_COMMIT();

    for (int t = 0; t < 8; t++) {
        CP_WAIT0();                 // K(t) landed (and any prior V consumed)
        __syncthreads();            // K(t) visible; EA/EG(t-1) consumed; VS free
        float* ksb = KS + (t & 1) * SWT_F;

        // stage V(t) (coalesced) — group 1
        sw_cp_tile(vs_addr, vcol + (size_t)t * 128 * OUTF, tid);
        CP_COMMIT();
        // prefetch K(t+1) — group 2
        if (t < 7)
            sw_cp_tile(ks_addr0 + (uint32_t)(((t + 1) & 1) * SWT_F * 4),
                       kcol + (size_t)(t + 1) * 128 * OUTF, tid);
        CP_COMMIT();

        // ---- phase A: Z1/Z2 = K @ W ----
        float z1[2][2][4], z2[2][2][4];
#pragma unroll
        for (int mi = 0; mi < 2; mi++)
#pragma unroll
            for (int nt = 0; nt < 2; nt++)
#pragma unroll
                for (int q = 0; q < 4; q++) { z1[mi][nt][q] = 0.f; z2[mi][nt][q] = 0.f; }
#pragma unroll
        for (int ks = 0; ks < 8; ks++) {
            const int kk = ks * 8;
            uint32_t a[2][4];
#pragma unroll
            for (int mi = 0; mi < 2; mi++) {
                const int rb = wm + mi * 16;
                a[mi][0] = __float_as_uint(ksb[(rb + g)     * LDS_W + kk + tg]);
                a[mi][1] = __float_as_uint(ksb[(rb + g + 8) * LDS_W + kk + tg]);
                a[mi][2] = __float_as_uint(ksb[(rb + g)     * LDS_W + kk + tg + 4]);
                a[mi][3] = __float_as_uint(ksb[(rb + g + 8) * LDS_W + kk + tg + 4]);
            }
#pragma unroll
            for (int nt = 0; nt < 2; nt++) {
                const int col = eh + nt * 8;
                uint32_t b0 = __float_as_uint(W1t[(col + g) * LDS_W + kk + tg]);
                uint32_t b1 = __float_as_uint(W1t[(col + g) * LDS_W + kk + tg + 4]);
                uint32_t c0 = __float_as_uint(W2t[(col + g) * LDS_W + kk + tg]);
                uint32_t c1 = __float_as_uint(W2t[(col + g) * LDS_W + kk + tg + 4]);
#pragma unroll
                for (int mi = 0; mi < 2; mi++) {
                    MMA_TF32(z1[mi][nt], a[mi][0], a[mi][1], a[mi][2], a[mi][3], b0, b1);
                    MMA_TF32(z2[mi][nt], a[mi][0], a[mi][1], a[mi][2], a[mi][3], c0, c1);
                }
            }
        }
        // V(t) must be visible to all threads before elementwise
        CP_WAIT1();                 // V(t) done (K(t+1) may still be in flight)
        __syncthreads();

        // ---- elementwise: ea, eg (v from smem) ----
#pragma unroll
        for (int mi = 0; mi < 2; mi++)
#pragma unroll
            for (int nt = 0; nt < 2; nt++)
#pragma unroll
                for (int rp = 0; rp < 2; rp++) {
                    const int row = wm + mi * 16 + g + rp * 8;
                    const int col = eh + nt * 8 + tg * 2;
                    float2 v2 = *(const float2*)&VS[row * LDS_W + col];
                    float zz2 = z2[mi][nt][rp * 2], zz1 = z1[mi][nt][rp * 2];
                    float ev  = ESC_CONST * v2.x;
                    float s   = 1.f / (1.f + __expf(-zz2));
                    float ea0 = ev * zz2 * s;
                    float eg0 = ev * zz1 * (s * (1.f + zz2 * (1.f - s)));
                    zz2 = z2[mi][nt][rp * 2 + 1]; zz1 = z1[mi][nt][rp * 2 + 1];
                    ev  = ESC_CONST * v2.y;
                    s   = 1.f / (1.f + __expf(-zz2));
                    float ea1 = ev * zz2 * s;
                    float eg1 = ev * zz1 * (s * (1.f + zz2 * (1.f - s)));
                    *(float2*)&EA[row * LDS_W + col] =
                        make_float2(__uint_as_float(f2tf32(ea0)), __uint_as_float(f2tf32(ea1)));
                    *(float2*)&EG[row * LDS_W + col] =
                        make_float2(__uint_as_float(f2tf32(eg0)), __uint_as_float(f2tf32(eg1)));
                }
        __syncthreads();
        // ---- phase B: G += K^T @ (EA or EG) ----
        const float* bbp = isW2 ? EG : EA;
#pragma unroll
        for (int ks = 0; ks < 16; ks++) {
            const int kk = ks * 8;
            uint32_t a0 = __float_as_uint(ksb[(kk + tg)     * LDS_W + ds + g]);
            uint32_t a1 = __float_as_uint(ksb[(kk + tg)     * LDS_W + ds + g + 8]);
            uint32_t a2 = __float_as_uint(ksb[(kk + tg + 4) * LDS_W + ds + g]);
            uint32_t a3 = __float_as_uint(ksb[(kk + tg + 4) * LDS_W + ds + g + 8]);
#pragma unroll
            for (int nt = 0; nt < 4; nt++) {
                const int nc = eh2 + nt * 8;
                uint32_t b0 = __float_as_uint(bbp[(kk + tg)     * LDS_W + nc + g]);
                uint32_t b1 = __float_as_uint(bbp[(kk + tg + 4) * LDS_W + nc + g]);
                MMA_TF32(G[nt], a0, a1, a2, a3, b0, b1);
            }
        }
    }

    // ---- column norms (over d) ----
#pragma unroll
    for (int nt = 0; nt < 4; nt++)
#pragma unroll
        for (int par = 0; par < 2; par++) {
            float s = G[nt][par] * G[nt][par] + G[nt][2 + par] * G[nt][2 + par];
            s += __shfl_xor_sync(0xffffffffu, s, 4);
            s += __shfl_xor_sync(0xffffffffu, s, 8);
            s += __shfl_xor_sync(0xffffffffu, s, 16);
            if (g == 0)
                atomicAdd(&CS[isW2 * 64 + eh2 + nt * 8 + tg * 2 + par], s);
        }
    __syncthreads();
    {
        float* wt = isW2 ? W2t : W1t;
#pragma unroll
        for (int nt = 0; nt < 4; nt++)
#pragma unroll
            for (int par = 0; par < 2; par++) {
                const int col = eh2 + nt * 8 + tg * 2 + par;
                float iv = 1.f / (sqrtf(CS[isW2 * 64 + col]) + 1.f);
                float n0 = wt[col * LDS_W + ds + g]     - G[nt][par]     * iv;
                float n1 = wt[col * LDS_W + ds + g + 8] - G[nt][2 + par] * iv;
                wt[col * LDS_W + ds + g]     = __uint_as_float(f2tf32(n0));
                wt[col * LDS_W + ds + g + 8] = __uint_as_float(f2tf32(n1));
            }
    }
    __syncthreads();

    // ---- store updated weights to global ----
    {
        float* w1u = g_w1u + (size_t)blockIdx.x * 4352;
        float* w2u = g_w2u + (size_t)blockIdx.x * 4352;
        for (int i = tid; i < 1088; i += 512) {
            *(float4*)&w1u[i * 4] = *(const float4*)&W1t[i * 4];
            *(float4*)&w2u[i * 4] = *(const float4*)&W2t[i * 4];
        }
    }
}

// ---------------------------------------------------------------------------
// Fused apply + dwc kernel: 256 threads, 2 CTAs/SM.
//   blocks [0, 768): x1 apply -> x1 = (Q @ W1u) * silu(Q @ W2u)
//   blocks [768, 1280): depthwise-conv update + apply (4 channels per block)
// ---------------------------------------------------------------------------
#define AP_KS (2 * 64 * LDS_W)
#define AP_BYTES ((4 * 64 * LDS_W) * 4)     // 69632 bytes (covers dwc's 49440)

__device__ void apply_x1_body(float* ap, int blk)
{
    float* W1t = ap;
    float* W2t = ap + SW_W2;
    float* KS  = ap + AP_KS;
    const uint32_t ks_addr0 = smem_u32(ap + AP_KS);

    const int bh = blk >> 1;
    const int half = blk & 1;
    const int b = bh / HH, h = bh % HH;
    const int tid = threadIdx.x;
    const int wid = tid >> 5, lane = tid & 31;
    const int g = lane >> 2, tg = lane & 3;
    const int wm = (wid & 3) * 16;
    const int eh = (wid >> 2) * 32;

    {
        const float* w1u = g_w1u + (size_t)bh * 4352;
        const float* w2u = g_w2u + (size_t)bh * 4352;
        for (int i = tid; i < 1088; i += 256) {
            *(float4*)&W1t[i * 4] = *(const float4*)&w1u[i * 4];
            *(float4*)&W2t[i * 4] = *(const float4*)&w2u[i * 4];
        }
    }

    const size_t row0 = (size_t)b * NSEQ + half * 512;
    const float* qcol = g_qkv + row0 * OUTF + h * DD;

#pragma unroll
    for (int i = 0; i < 4; i++) {
        int idx = tid + i * 256;
        int r = idx >> 4, c4 = (idx & 15) << 2;
        cp16(ks_addr0 + (uint32_t)(r * LDS_W + c4) * 4u, qcol + (size_t)r * OUTF + c4);
    }
    CP_COMMIT();

    for (int t = 0; t < 8; t++) {
        CP_WAIT0();
        __syncthreads();
        const float* ksb = KS + (t & 1) * (64 * LDS_W);
        if (t < 7) {
            const float* src = qcol + (size_t)(t + 1) * 64 * OUTF;
            uint32_t dst = ks_addr0 + (uint32_t)(((t + 1) & 1) * 64 * LDS_W * 4);
#pragma unroll
            for (int i = 0; i < 4; i++) {
                int idx = tid + i * 256;
                int r = idx >> 4, c4 = (idx & 15) << 2;
                cp16(dst + (uint32_t)(r * LDS_W + c4) * 4u, src + (size_t)r * OUTF + c4);
            }
        }
        CP_COMMIT();

        float y1[4][4], y2[4][4];
#pragma unroll
        for (int nt = 0; nt < 4; nt++)
#pragma unroll
            for (int q = 0; q < 4; q++) { y1[nt][q] = 0.f; y2[nt][q] = 0.f; }
#pragma unroll
        for (int ks = 0; ks < 8; ks++) {
            const int kk = ks * 8;
            uint32_t a0 = __float_as_uint(ksb[(wm + g)     * LDS_W + kk + tg]);
            uint32_t a1 = __float_as_uint(ksb[(wm + g + 8) * LDS_W + kk + tg]);
            uint32_t a2 = __float_as_uint(ksb[(wm + g)     * LDS_W + kk + tg + 4]);
            uint32_t a3 = __float_as_uint(ksb[(wm + g + 8) * LDS_W + kk + tg + 4]);
#pragma unroll
            for (int nt = 0; nt < 4; nt++) {
                const int col = eh + nt * 8;
                uint32_t b0 = __float_as_uint(W1t[(col + g) * LDS_W + kk + tg]);
                uint32_t b1 = __float_as_uint(W1t[(col + g) * LDS_W + kk + tg + 4]);
                uint32_t c0 = __float_as_uint(W2t[(col + g) * LDS_W + kk + tg]);
                uint32_t c1 = __float_as_uint(W2t[(col + g) * LDS_W + kk + tg + 4]);
                MMA_TF32(y1[nt], a0, a1, a2, a3, b0, b1);
                MMA_TF32(y2[nt], a0, a1, a2, a3, c0, c1);
            }
        }
#pragma unroll
        for (int nt = 0; nt < 4; nt++)
#pragma unroll
            for (int rp = 0; rp < 2; rp++) {
                const size_t row = row0 + t * 64 + wm + g + rp * 8;
                const int col = eh + nt * 8 + tg * 2;
                float yv = y2[nt][rp * 2];
                float s  = 1.f / (1.f + __expf(-yv));
                float o0 = y1[nt][rp * 2] * yv * s;
                yv = y2[nt][rp * 2 + 1];
                s  = 1.f / (1.f + __expf(-yv));
                float o1 = y1[nt][rp * 2 + 1] * yv * s;
                *(float2*)&g_xcat[row * XCATC + h * DD + col] = make_float2(o0, o1);
            }
    }
}

__device__ void dwc_x2_body(float* dsm, int blk, const float* __restrict__ w3)
{
    float* q2s  = dsm;              // [1024][4]
    float* k2s  = dsm + 4096;
    float* es   = dsm + 8192;
    float* gsum = dsm + 12288;      // [4][9]
    float* w3s  = dsm + 12324;      // [4][9]

    const int b = blk >> 4;
    const int dq = blk & 15;
    const int d0c = dq * 4;
    const int tid = threadIdx.x;
    const int lane = tid & 31;
    const size_t rowbase = (size_t)b * NSEQ;

#pragma unroll
    for (int it = 0; it < 4; it++) {
        int p = tid + it * 256;
        const float* base = &g_qkv[(rowbase + p) * OUTF + 3 * CC + d0c];
        float4 q = *(const float4*)base;
        float4 k = *(const float4*)(base + DD);
        float4 v = *(const float4*)(base + 2 * DD);
        *(float4*)&q2s[p * 4] = q;
        *(float4*)&k2s[p * 4] = k;
        *(float4*)&es[p * 4] = make_float4(v.x * ESC_CONST, v.y * ESC_CONST,
                                           v.z * ESC_CONST, v.w * ESC_CONST);
    }
    if (tid < 36) gsum[tid] = 0.f;
    __syncthreads();

    float acc[4][9];
#pragma unroll
    for (int dl = 0; dl < 4; dl++)
#pragma unroll
        for (int j = 0; j < 9; j++) acc[dl][j] = 0.f;

#pragma unroll
    for (int it = 0; it < 4; it++) {
        int p = tid + it * 256;
        int y = p >> 5, x = p & 31;
        float4 e4 = *(const float4*)&es[p * 4];
#pragma unroll
        for (int ky = 0; ky < 3; ky++) {
            int yy = y + ky - 1;
            if (yy < 0 || yy > 31) continue;
#pragma unroll
            for (int kx = 0; kx < 3; kx++) {
                int xx = x + kx - 1;
                if (xx < 0 || xx > 31) continue;
                float4 k4 = *(const float4*)&k2s[(yy * 32 + xx) * 4];
                int j = ky * 3 + kx;
                acc[0][j] += k4.x * e4.x;
                acc[1][j] += k4.y * e4.y;
                acc[2][j] += k4.z * e4.z;
                acc[3][j] += k4.w * e4.w;
            }
        }
    }
#pragma unroll
    for (int dl = 0; dl < 4; dl++)
#pragma unroll
        for (int j = 0; j < 9; j++) {
            float v = acc[dl][j];
#pragma unroll
            for (int o = 16; o > 0; o >>= 1) v += __shfl_down_sync(0xffffffffu, v, o);
            if (lane == 0) atomicAdd(&gsum[dl * 9 + j], v);
        }
    __syncthreads();
    if (tid < 4) {
        float nrm = 0.f;
#pragma unroll
        for (int j = 0; j < 9; j++) nrm += gsum[tid * 9 + j] * gsum[tid * 9 + j];
        float inv = 1.f / (sqrtf(nrm) + 1.f);
#pragma unroll
        for (int j = 0; j < 9; j++)
            w3s[tid * 9 + j] = w3[(d0c + tid) * 9 + j] - gsum[tid * 9 + j] * inv;
    }
    __syncthreads();

#pragma unroll
    for (int it = 0; it < 4; it++) {
        int p = tid + it * 256;
        int y = p >> 5, x = p & 31;
        float4 a = make_float4(0.f, 0.f, 0.f, 0.f);
#pragma unroll
        for (int ky = 0; ky < 3; ky++) {
            int yy = y + ky - 1;
            if (yy < 0 || yy > 31) continue;
#pragma unroll
            for (int kx = 0; kx < 3; kx++) {
                int xx = x + kx - 1;
                if (xx < 0 || xx > 31) continue;
                float4 q4 = *(const float4*)&q2s[(yy * 32 + xx) * 4];
                int j = ky * 3 + kx;
                a.x += q4.x * w3s[j];
                a.y += q4.y * w3s[9 + j];
                a.z += q4.z * w3s[18 + j];
                a.w += q4.w * w3s[27 + j];
            }
        }
        *(float4*)&g_xcat[(rowbase + p) * XCATC + CC + d0c] = a;
    }
}

__global__ __launch_bounds__(256, 2) void apply_dwc_kernel(const float* __restrict__ w3)
{
    extern __shared__ float ap[];
    if (blockIdx.x < BB * HH * 2)
        apply_x1_body(ap, blockIdx.x);
    else
        dwc_x2_body(ap, blockIdx.x - BB * HH * 2, w3);
}

// ---------------------------------------------------------------------------
// Launch (single stream — graph-capture safe)
// ---------------------------------------------------------------------------
extern "C" void kernel_launch(void* const* d_in, const int* in_sizes, int n_in,
                              void* d_out, int out_size)
{
    const float* x      = (const float*)d_in[0];
    const float* W_qkv  = (const float*)d_in[1];
    const float* b_qkv  = (const float*)d_in[2];
    const float* w1     = (const float*)d_in[3];
    const float* w2     = (const float*)d_in[4];
    const float* w3     = (const float*)d_in[5];
    const float* proj_W = (const float*)d_in[6];
    const float* proj_b = (const float*)d_in[7];
    float* out = (float*)d_out;

    float *qkv, *xcat, *Wt1, *Wt2;
    cudaGetSymbolAddress((void**)&qkv,  g_qkv);
    cudaGetSymbolAddress((void**)&xcat, g_xcat);
    cudaGetSymbolAddress((void**)&Wt1,  g_Wt1);
    cudaGetSymbolAddress((void**)&Wt2,  g_Wt2);

    cudaFuncSetAttribute(gemm_mma_kernel, cudaFuncAttributeMaxDynamicSharedMemorySize, GSMEM_BYTES);
    cudaFuncSetAttribute(swiglu_grad_kernel, cudaFuncAttributeMaxDynamicSharedMemorySize, SW_BYTES);
    cudaFuncSetAttribute(apply_dwc_kernel, cudaFuncAttributeMaxDynamicSharedMemorySize, AP_BYTES);

    // Transposes: Wt1[n][k] = W_qkv[k][n] (pad to 2560 rows); Wt2[n][k] = proj_W[k][n]
    {
        dim3 blk(32, 8);
        transpose_pad_kernel<<<dim3(2560 / 32, CC / 32), blk>>>(W_qkv, Wt1, CC, OUTF, 2560);
        transpose_pad_kernel<<<dim3(CC / 32, XCATC / 32), blk>>>(proj_W, Wt2, XCATC, CC, CC);
    }
    // GEMM1: qkv = x @ W_qkv + b_qkv   [32768,768] x [768,2496]
    {
        dim3 grid(2560 / NTG, MROWS / MT);
        gemm_mma_kernel<<<grid, 256, GSMEM_BYTES>>>(x, Wt1, b_qkv, qkv, MROWS, OUTF, CC);
    }
    // SwiGLU gradient + weight update (V staged in smem)
    swiglu_grad_kernel<<<BB * HH, 512, SW_BYTES>>>(w1, w2);
    // Fused x1 apply + dwc (dwc blocks fill apply's tail waves)
    apply_dwc_kernel<<<BB * HH * 2 + BB * 16, 256, AP_BYTES>>>(w3);
    // GEMM2: out = xcat @ proj_W + proj_b   [32768,832] x [832,768]
    {
        dim3 grid(CC / NTG, MROWS / MT);
        gemm_mma_kernel<<<grid, 256, GSMEM_BYTES>>>(xcat, Wt2, proj_b, out, MROWS, CC, XCATC);
    }
}

// round 17
// speedup vs baseline: 1.1498x; 1.1498x over previous
#include <cuda_runtime.h>
#include <cuda_bf16.h>
#include <math.h>
#include <stdint.h>

// Problem constants (fixed by the dataset)
#define BB   32
#define NSEQ 1024
#define CC   768
#define HH   12
#define DD   64
#define OUTF 2496            // 3C + 3D
#define XCATC 832            // C + D
#define MROWS (BB*NSEQ)      // 32768

#define ESC_CONST (-(1.0f/1024.0f)*(1.0f/3.0f))

// GEMM tiling (round-15 proven config: 128x128 tile, 4 warps, 3 stages)
#define MT 128
#define NT 128
#define KC 32
#define STAGE_F (128 * 32)            // floats per (A or B) tile
#define STAGE_BYTES (2 * STAGE_F * 4) // 32768 bytes per stage (A+B)

// Scratch (device globals -> no allocation)
__device__ float g_qkv[(size_t)MROWS * OUTF];     // [32768, 2496]
__device__ float g_xcat[(size_t)MROWS * XCATC];   // [32768, 832]
__device__ float g_Wt1[(size_t)2560 * CC];        // W_qkv^T padded to 2560 rows
__device__ float g_Wt2[(size_t)CC * XCATC];       // proj_W^T [768, 832]
__device__ float g_w1u[(size_t)BB * HH * 4352];   // updated W1 [e][d], LD=68
__device__ float g_w2u[(size_t)BB * HH * 4352];   // updated W2 [e][d], LD=68

__device__ __forceinline__ uint32_t smem_u32(const void* p) {
    uint32_t a;
    asm("{ .reg .u64 t; cvta.to.shared.u64 t, %1; cvt.u32.u64 %0, t; }" : "=r"(a) : "l"(p));
    return a;
}
__device__ __forceinline__ void cp16(uint32_t dst, const void* src) {
    asm volatile("cp.async.cg.shared.global [%0], [%1], 16;" :: "r"(dst), "l"(src));
}
#define CP_COMMIT() asm volatile("cp.async.commit_group;" ::: "memory")
#define CP_WAIT1()  asm volatile("cp.async.wait_group 1;" ::: "memory")
#define CP_WAIT0()  asm volatile("cp.async.wait_group 0;" ::: "memory")

__device__ __forceinline__ uint32_t f2tf32(float f) {
    uint32_t r;
    asm("cvt.rna.tf32.f32 %0, %1;" : "=r"(r) : "f"(f));
    return r;
}

#define MMA_TF32(d, a0, a1, a2, a3, b0, b1) \
    asm volatile( \
        "mma.sync.aligned.m16n8k8.row.col.f32.tf32.tf32.f32 " \
        "{%0,%1,%2,%3}, {%4,%5,%6,%7}, {%8,%9}, {%0,%1,%2,%3};" \
        : "+f"((d)[0]), "+f"((d)[1]), "+f"((d)[2]), "+f"((d)[3]) \
        : "r"(a0), "r"(a1), "r"(a2), "r"(a3), "r"(b0), "r"(b1))

// swizzled smem read (GEMM): row r (stride 32 floats), col c
__device__ __forceinline__ float ldsw(const float* s, int r, int c) {
    return s[r * 32 + ((((c >> 2) ^ (r & 7)) << 2) | (c & 3))];
}

// ---------------------------------------------------------------------------
// Transpose with row padding: out[n][k] = in[k][n]; zero rows n in [inC, outR)
// ---------------------------------------------------------------------------
__global__ void transpose_pad_kernel(const float* __restrict__ in, float* __restrict__ out,
                                     int inR, int inC, int outR)
{
    __shared__ float t[32][33];
    int kb = blockIdx.y * 32, nb = blockIdx.x * 32;
    int x = threadIdx.x, y = threadIdx.y;
    for (int i = y; i < 32; i += 8) {
        int k = kb + i, n = nb + x;
        t[i][x] = (k < inR && n < inC) ? in[(size_t)k * inC + n] : 0.f;
    }
    __syncthreads();
    for (int i = y; i < 32; i += 8) {
        int n = nb + i, k = kb + x;
        if (n < outR && k < inR) out[(size_t)n * inR + k] = t[x][i];
    }
}

// ---------------------------------------------------------------------------
// TF32 mma.sync GEMM, cp.async 3-stage pipeline, 128 threads (4 warps),
// 64x64 warp tiles. (round-15 proven version — DO NOT CHANGE)
// ---------------------------------------------------------------------------
__device__ __forceinline__ void fill_stage(uint32_t sbase,
    const float* __restrict__ A, const float* __restrict__ Bt,
    int m0, int n0, int K, int k0, int tid)
{
    const float* Ab = A + (size_t)m0 * K + k0;
#pragma unroll
    for (int i = 0; i < 8; i++) {
        int idx = tid + i * 128;
        int r = idx >> 3, q = idx & 7;
        uint32_t off = (uint32_t)(r * 128 + ((q ^ (r & 7)) * 16));
        cp16(sbase + off, Ab + (size_t)r * K + q * 4);
    }
    const float* Bb = Bt + (size_t)n0 * K + k0;
#pragma unroll
    for (int i = 0; i < 8; i++) {
        int idx = tid + i * 128;
        int r = idx >> 3, q = idx & 7;
        uint32_t off = (uint32_t)(r * 128 + ((q ^ (r & 7)) * 16));
        cp16(sbase + (uint32_t)STAGE_F * 4 + off, Bb + (size_t)r * K + q * 4);
    }
}

__global__ __launch_bounds__(128) void gemm_mma_kernel(
    const float* __restrict__ A, const float* __restrict__ Bt,
    const float* __restrict__ bias, float* __restrict__ C,
    int M, int Nn, int K)
{
    extern __shared__ float sm[];
    const uint32_t sb = smem_u32(sm);

    const int tid = threadIdx.x;
    const int wid = tid >> 5, lane = tid & 31;
    const int g = lane >> 2, tg = lane & 3;
    const int wm = (wid >> 1) * 64;
    const int wn = (wid & 1) * 64;
    const int m0 = blockIdx.y * MT;
    const int n0 = blockIdx.x * NT;
    const int nk = K / KC;

    float acc[4][8][4];
#pragma unroll
    for (int mi = 0; mi < 4; mi++)
#pragma unroll
        for (int nj = 0; nj < 8; nj++)
#pragma unroll
            for (int q = 0; q < 4; q++) acc[mi][nj][q] = 0.f;

    fill_stage(sb, A, Bt, m0, n0, K, 0, tid);
    CP_COMMIT();
    fill_stage(sb + STAGE_BYTES, A, Bt, m0, n0, K, KC, tid);
    CP_COMMIT();

    for (int kt = 0; kt < nk; kt++) {
        CP_WAIT1();
        __syncthreads();
        if (kt + 2 < nk)
            fill_stage(sb + (uint32_t)((kt + 2) % 3) * STAGE_BYTES,
                       A, Bt, m0, n0, K, (kt + 2) * KC, tid);
        CP_COMMIT();

        const float* a_s = sm + (size_t)(kt % 3) * (2 * STAGE_F);
        const float* b_s = a_s + STAGE_F;
#pragma unroll
        for (int ks = 0; ks < 4; ks++) {
            const int kk = ks * 8;
            uint32_t a[4][4], b[8][2];
#pragma unroll
            for (int mi = 0; mi < 4; mi++) {
                const int row = wm + mi * 16;
                a[mi][0] = __float_as_uint(ldsw(a_s, row + g,     kk + tg));
                a[mi][1] = __float_as_uint(ldsw(a_s, row + g + 8, kk + tg));
                a[mi][2] = __float_as_uint(ldsw(a_s, row + g,     kk + tg + 4));
                a[mi][3] = __float_as_uint(ldsw(a_s, row + g + 8, kk + tg + 4));
            }
#pragma unroll
            for (int nj = 0; nj < 8; nj++) {
                const int col = wn + nj * 8;
                b[nj][0] = __float_as_uint(ldsw(b_s, col + g, kk + tg));
                b[nj][1] = __float_as_uint(ldsw(b_s, col + g, kk + tg + 4));
            }
#pragma unroll
            for (int mi = 0; mi < 4; mi++)
#pragma unroll
                for (int nj = 0; nj < 8; nj++)
                    MMA_TF32(acc[mi][nj], a[mi][0], a[mi][1], a[mi][2], a[mi][3],
                             b[nj][0], b[nj][1]);
        }
        __syncthreads();
    }

    // epilogue
#pragma unroll
    for (int nj = 0; nj < 8; nj++) {
        const int gc = n0 + wn + nj * 8 + tg * 2;
        if (gc >= Nn) continue;
        const float bx = bias[gc], by = bias[gc + 1];
#pragma unroll
        for (int mi = 0; mi < 4; mi++) {
            const int row = m0 + wm + mi * 16 + g;
            float2 s0 = make_float2(acc[mi][nj][0] + bx, acc[mi][nj][1] + by);
            float2 s1 = make_float2(acc[mi][nj][2] + bx, acc[mi][nj][3] + by);
            *(float2*)&C[(size_t)row * Nn + gc] = s0;
            *(float2*)&C[(size_t)(row + 8) * Nn + gc] = s1;
        }
    }
}

// ---------------------------------------------------------------------------
// SwiGLU gradient + weight update (phases A+B only), 512 threads.
// V staged in smem. EA/EG now stored TRANSPOSED [e][n] with LD=132 so that
// phase-B B-fragment loads and elementwise stores are bank-conflict-free.
// ---------------------------------------------------------------------------
#define LDS_W 68
#define LDE   132                    // E-matrix LD: (4(nc+g)+kk+tg)%32 bijective
#define SWT_F (128 * LDS_W)          // 8704 floats per 128-row K tile
#define SWE_F (64 * LDE)             // 8448 floats per E matrix
#define SW_W2 (64 * LDS_W)           // 4352
#define SW_EA (2 * 64 * LDS_W)       // 8704
#define SW_EG (SW_EA + SWE_F)        // 17152
#define SW_KS (SW_EG + SWE_F)        // 25600
#define SW_CS (SW_KS + 2 * SWT_F)    // 43008
#define SW_V  (SW_CS + 128)          // 43136
#define SW_TOT (SW_V + SWT_F)        // 51840 floats
#define SW_BYTES (SW_TOT * 4)        // 207360 bytes

__device__ __forceinline__ void sw_cp_tile(uint32_t dst, const float* src, int tid) {
#pragma unroll
    for (int i = 0; i < 4; i++) {
        int idx = tid + i * 512;
        int r = idx >> 4, c4 = (idx & 15) << 2;
        cp16(dst + (uint32_t)(r * LDS_W + c4) * 4u, src + (size_t)r * OUTF + c4);
    }
}

__global__ __launch_bounds__(512) void swiglu_grad_kernel(
    const float* __restrict__ w1, const float* __restrict__ w2)
{
    extern __shared__ float sw[];
    float* W1t = sw;
    float* W2t = sw + SW_W2;
    float* EAt = sw + SW_EA;     // [e][n], LD=132
    float* EGt = sw + SW_EG;     // [e][n], LD=132
    float* KS  = sw + SW_KS;
    float* CS  = sw + SW_CS;
    float* VS  = sw + SW_V;
    const uint32_t ks_addr0 = smem_u32(sw + SW_KS);
    const uint32_t vs_addr  = smem_u32(sw + SW_V);

    const int b = blockIdx.x / HH, h = blockIdx.x % HH;
    const int tid = threadIdx.x;
    const int wid = tid >> 5, lane = tid & 31;
    const int g = lane >> 2, tg = lane & 3;
    const int wm = (wid & 3) * 32;
    const int eh = (wid >> 2) * 16;
    const int w8 = wid & 7;
    const int ds = (w8 & 3) * 16;
    const int eh2 = (w8 >> 2) * 32;
    const int isW2 = wid >> 3;

    for (int i = tid; i < DD * DD; i += 512) {
        int d = i >> 6, e = i & 63;
        W1t[e * LDS_W + d] = __uint_as_float(f2tf32(w1[h * DD * DD + i]));
        W2t[e * LDS_W + d] = __uint_as_float(f2tf32(w2[h * DD * DD + i]));
    }
    if (tid < 128) CS[tid] = 0.f;

    float G[4][4];
#pragma unroll
    for (int nt = 0; nt < 4; nt++)
#pragma unroll
        for (int q = 0; q < 4; q++) G[nt][q] = 0.f;

    const size_t rowbase = (size_t)b * NSEQ;
    const float* kcol = g_qkv + rowbase * OUTF + CC + h * DD;
    const float* vcol = g_qkv + rowbase * OUTF + 2 * CC + h * DD;

    sw_cp_tile(ks_addr0, kcol, tid);
    CP_COMMIT();

    for (int t = 0; t < 8; t++) {
        CP_WAIT0();                 // K(t) landed (and prior V consumed)
        __syncthreads();            // K(t) visible; EAt/EGt(t-1) consumed; VS free
        float* ksb = KS + (t & 1) * SWT_F;

        // stage V(t) (coalesced) — group 1
        sw_cp_tile(vs_addr, vcol + (size_t)t * 128 * OUTF, tid);
        CP_COMMIT();
        // prefetch K(t+1) — group 2
        if (t < 7)
            sw_cp_tile(ks_addr0 + (uint32_t)(((t + 1) & 1) * SWT_F * 4),
                       kcol + (size_t)(t + 1) * 128 * OUTF, tid);
        CP_COMMIT();

        // ---- phase A: Z1/Z2 = K @ W ----
        float z1[2][2][4], z2[2][2][4];
#pragma unroll
        for (int mi = 0; mi < 2; mi++)
#pragma unroll
            for (int nt = 0; nt < 2; nt++)
#pragma unroll
                for (int q = 0; q < 4; q++) { z1[mi][nt][q] = 0.f; z2[mi][nt][q] = 0.f; }
#pragma unroll
        for (int ks = 0; ks < 8; ks++) {
            const int kk = ks * 8;
            uint32_t a[2][4];
#pragma unroll
            for (int mi = 0; mi < 2; mi++) {
                const int rb = wm + mi * 16;
                a[mi][0] = __float_as_uint(ksb[(rb + g)     * LDS_W + kk + tg]);
                a[mi][1] = __float_as_uint(ksb[(rb + g + 8) * LDS_W + kk + tg]);
                a[mi][2] = __float_as_uint(ksb[(rb + g)     * LDS_W + kk + tg + 4]);
                a[mi][3] = __float_as_uint(ksb[(rb + g + 8) * LDS_W + kk + tg + 4]);
            }
#pragma unroll
            for (int nt = 0; nt < 2; nt++) {
                const int col = eh + nt * 8;
                uint32_t b0 = __float_as_uint(W1t[(col + g) * LDS_W + kk + tg]);
                uint32_t b1 = __float_as_uint(W1t[(col + g) * LDS_W + kk + tg + 4]);
                uint32_t c0 = __float_as_uint(W2t[(col + g) * LDS_W + kk + tg]);
                uint32_t c1 = __float_as_uint(W2t[(col + g) * LDS_W + kk + tg + 4]);
#pragma unroll
                for (int mi = 0; mi < 2; mi++) {
                    MMA_TF32(z1[mi][nt], a[mi][0], a[mi][1], a[mi][2], a[mi][3], b0, b1);
                    MMA_TF32(z2[mi][nt], a[mi][0], a[mi][1], a[mi][2], a[mi][3], c0, c1);
                }
            }
        }
        // V(t) must be visible to all threads before elementwise
        CP_WAIT1();                 // V(t) done (K(t+1) may still be in flight)
        __syncthreads();

        // ---- elementwise: ea, eg (v from smem) -> EAt/EGt transposed [e][n] ----
#pragma unroll
        for (int mi = 0; mi < 2; mi++)
#pragma unroll
            for (int nt = 0; nt < 2; nt++)
#pragma unroll
                for (int rp = 0; rp < 2; rp++) {
                    const int row = wm + mi * 16 + g + rp * 8;      // n index
                    const int col = eh + nt * 8 + tg * 2;            // e index
                    float2 v2 = *(const float2*)&VS[row * LDS_W + col];
                    float zz2 = z2[mi][nt][rp * 2], zz1 = z1[mi][nt][rp * 2];
                    float ev  = ESC_CONST * v2.x;
                    float s   = 1.f / (1.f + __expf(-zz2));
                    float ea0 = ev * zz2 * s;
                    float eg0 = ev * zz1 * (s * (1.f + zz2 * (1.f - s)));
                    zz2 = z2[mi][nt][rp * 2 + 1]; zz1 = z1[mi][nt][rp * 2 + 1];
                    ev  = ESC_CONST * v2.y;
                    s   = 1.f / (1.f + __expf(-zz2));
                    float ea1 = ev * zz2 * s;
                    float eg1 = ev * zz1 * (s * (1.f + zz2 * (1.f - s)));
                    EAt[col * LDE + row]       = __uint_as_float(f2tf32(ea0));
                    EAt[(col + 1) * LDE + row] = __uint_as_float(f2tf32(ea1));
                    EGt[col * LDE + row]       = __uint_as_float(f2tf32(eg0));
                    EGt[(col + 1) * LDE + row] = __uint_as_float(f2tf32(eg1));
                }
        __syncthreads();
        // ---- phase B: G += K^T @ (EA or EG); B frags row-indexed in [e][n] ----
        const float* bbp = isW2 ? EGt : EAt;
#pragma unroll
        for (int ks = 0; ks < 16; ks++) {
            const int kk = ks * 8;
            uint32_t a0 = __float_as_uint(ksb[(kk + tg)     * LDS_W + ds + g]);
            uint32_t a1 = __float_as_uint(ksb[(kk + tg)     * LDS_W + ds + g + 8]);
            uint32_t a2 = __float_as_uint(ksb[(kk + tg + 4) * LDS_W + ds + g]);
            uint32_t a3 = __float_as_uint(ksb[(kk + tg + 4) * LDS_W + ds + g + 8]);
#pragma unroll
            for (int nt = 0; nt < 4; nt++) {
                const int nc = eh2 + nt * 8;
                uint32_t b0 = __float_as_uint(bbp[(nc + g) * LDE + kk + tg]);
                uint32_t b1 = __float_as_uint(bbp[(nc + g) * LDE + kk + tg + 4]);
                MMA_TF32(G[nt], a0, a1, a2, a3, b0, b1);
            }
        }
    }

    // ---- column norms (over d) ----
#pragma unroll
    for (int nt = 0; nt < 4; nt++)
#pragma unroll
        for (int par = 0; par < 2; par++) {
            float s = G[nt][par] * G[nt][par] + G[nt][2 + par] * G[nt][2 + par];
            s += __shfl_xor_sync(0xffffffffu, s, 4);
            s += __shfl_xor_sync(0xffffffffu, s, 8);
            s += __shfl_xor_sync(0xffffffffu, s, 16);
            if (g == 0)
                atomicAdd(&CS[isW2 * 64 + eh2 + nt * 8 + tg * 2 + par], s);
        }
    __syncthreads();
    {
        float* wt = isW2 ? W2t : W1t;
#pragma unroll
        for (int nt = 0; nt < 4; nt++)
#pragma unroll
            for (int par = 0; par < 2; par++) {
                const int col = eh2 + nt * 8 + tg * 2 + par;
                float iv = 1.f / (sqrtf(CS[isW2 * 64 + col]) + 1.f);
                float n0 = wt[col * LDS_W + ds + g]     - G[nt][par]     * iv;
                float n1 = wt[col * LDS_W + ds + g + 8] - G[nt][2 + par] * iv;
                wt[col * LDS_W + ds + g]     = __uint_as_float(f2tf32(n0));
                wt[col * LDS_W + ds + g + 8] = __uint_as_float(f2tf32(n1));
            }
    }
    __syncthreads();

    // ---- store updated weights to global ----
    {
        float* w1u = g_w1u + (size_t)blockIdx.x * 4352;
        float* w2u = g_w2u + (size_t)blockIdx.x * 4352;
        for (int i = tid; i < 1088; i += 512) {
            *(float4*)&w1u[i * 4] = *(const float4*)&W1t[i * 4];
            *(float4*)&w2u[i * 4] = *(const float4*)&W2t[i * 4];
        }
    }
}

// ---------------------------------------------------------------------------
// Fused apply + dwc kernel: 256 threads, 2 CTAs/SM.
//   blocks [0, 768): x1 apply -> x1 = (Q @ W1u) * silu(Q @ W2u)
//   blocks [768, 1280): depthwise-conv update + apply (4 channels per block)
// ---------------------------------------------------------------------------
#define AP_KS (2 * 64 * LDS_W)
#define AP_BYTES ((4 * 64 * LDS_W) * 4)     // 69632 bytes (covers dwc's 49440)

__device__ void apply_x1_body(float* ap, int blk)
{
    float* W1t = ap;
    float* W2t = ap + SW_W2;
    float* KS  = ap + AP_KS;
    const uint32_t ks_addr0 = smem_u32(ap + AP_KS);

    const int bh = blk >> 1;
    const int half = blk & 1;
    const int b = bh / HH, h = bh % HH;
    const int tid = threadIdx.x;
    const int wid = tid >> 5, lane = tid & 31;
    const int g = lane >> 2, tg = lane & 3;
    const int wm = (wid & 3) * 16;
    const int eh = (wid >> 2) * 32;

    {
        const float* w1u = g_w1u + (size_t)bh * 4352;
        const float* w2u = g_w2u + (size_t)bh * 4352;
        for (int i = tid; i < 1088; i += 256) {
            *(float4*)&W1t[i * 4] = *(const float4*)&w1u[i * 4];
            *(float4*)&W2t[i * 4] = *(const float4*)&w2u[i * 4];
        }
    }

    const size_t row0 = (size_t)b * NSEQ + half * 512;
    const float* qcol = g_qkv + row0 * OUTF + h * DD;

#pragma unroll
    for (int i = 0; i < 4; i++) {
        int idx = tid + i * 256;
        int r = idx >> 4, c4 = (idx & 15) << 2;
        cp16(ks_addr0 + (uint32_t)(r * LDS_W + c4) * 4u, qcol + (size_t)r * OUTF + c4);
    }
    CP_COMMIT();

    for (int t = 0; t < 8; t++) {
        CP_WAIT0();
        __syncthreads();
        const float* ksb = KS + (t & 1) * (64 * LDS_W);
        if (t < 7) {
            const float* src = qcol + (size_t)(t + 1) * 64 * OUTF;
            uint32_t dst = ks_addr0 + (uint32_t)(((t + 1) & 1) * 64 * LDS_W * 4);
#pragma unroll
            for (int i = 0; i < 4; i++) {
                int idx = tid + i * 256;
                int r = idx >> 4, c4 = (idx & 15) << 2;
                cp16(dst + (uint32_t)(r * LDS_W + c4) * 4u, src + (size_t)r * OUTF + c4);
            }
        }
        CP_COMMIT();

        float y1[4][4], y2[4][4];
#pragma unroll
        for (int nt = 0; nt < 4; nt++)
#pragma unroll
            for (int q = 0; q < 4; q++) { y1[nt][q] = 0.f; y2[nt][q] = 0.f; }
#pragma unroll
        for (int ks = 0; ks < 8; ks++) {
            const int kk = ks * 8;
            uint32_t a0 = __float_as_uint(ksb[(wm + g)     * LDS_W + kk + tg]);
            uint32_t a1 = __float_as_uint(ksb[(wm + g + 8) * LDS_W + kk + tg]);
            uint32_t a2 = __float_as_uint(ksb[(wm + g)     * LDS_W + kk + tg + 4]);
            uint32_t a3 = __float_as_uint(ksb[(wm + g + 8) * LDS_W + kk + tg + 4]);
#pragma unroll
            for (int nt = 0; nt < 4; nt++) {
                const int col = eh + nt * 8;
                uint32_t b0 = __float_as_uint(W1t[(col + g) * LDS_W + kk + tg]);
                uint32_t b1 = __float_as_uint(W1t[(col + g) * LDS_W + kk + tg + 4]);
                uint32_t c0 = __float_as_uint(W2t[(col + g) * LDS_W + kk + tg]);
                uint32_t c1 = __float_as_uint(W2t[(col + g) * LDS_W + kk + tg + 4]);
                MMA_TF32(y1[nt], a0, a1, a2, a3, b0, b1);
                MMA_TF32(y2[nt], a0, a1, a2, a3, c0, c1);
            }
        }
#pragma unroll
        for (int nt = 0; nt < 4; nt++)
#pragma unroll
            for (int rp = 0; rp < 2; rp++) {
                const size_t row = row0 + t * 64 + wm + g + rp * 8;
                const int col = eh + nt * 8 + tg * 2;
                float yv = y2[nt][rp * 2];
                float s  = 1.f / (1.f + __expf(-yv));
                float o0 = y1[nt][rp * 2] * yv * s;
                yv = y2[nt][rp * 2 + 1];
                s  = 1.f / (1.f + __expf(-yv));
                float o1 = y1[nt][rp * 2 + 1] * yv * s;
                *(float2*)&g_xcat[row * XCATC + h * DD + col] = make_float2(o0, o1);
            }
    }
}

__device__ void dwc_x2_body(float* dsm, int blk, const float* __restrict__ w3)
{
    float* q2s  = dsm;              // [1024][4]
    float* k2s  = dsm + 4096;
    float* es   = dsm + 8192;
    float* gsum = dsm + 12288;      // [4][9]
    float* w3s  = dsm + 12324;      // [4][9]

    const int b = blk >> 4;
    const int dq = blk & 15;
    const int d0c = dq * 4;
    const int tid = threadIdx.x;
    const int lane = tid & 31;
    const size_t rowbase = (size_t)b * NSEQ;

#pragma unroll
    for (int it = 0; it < 4; it++) {
        int p = tid + it * 256;
        const float* base = &g_qkv[(rowbase + p) * OUTF + 3 * CC + d0c];
        float4 q = *(const float4*)base;
        float4 k = *(const float4*)(base + DD);
        float4 v = *(const float4*)(base + 2 * DD);
        *(float4*)&q2s[p * 4] = q;
        *(float4*)&k2s[p * 4] = k;
        *(float4*)&es[p * 4] = make_float4(v.x * ESC_CONST, v.y * ESC_CONST,
                                           v.z * ESC_CONST, v.w * ESC_CONST);
    }
    if (tid < 36) gsum[tid] = 0.f;
    __syncthreads();

    float acc[4][9];
#pragma unroll
    for (int dl = 0; dl < 4; dl++)
#pragma unroll
        for (int j = 0; j < 9; j++) acc[dl][j] = 0.f;

#pragma unroll
    for (int it = 0; it < 4; it++) {
        int p = tid + it * 256;
        int y = p >> 5, x = p & 31;
        float4 e4 = *(const float4*)&es[p * 4];
#pragma unroll
        for (int ky = 0; ky < 3; ky++) {
            int yy = y + ky - 1;
            if (yy < 0 || yy > 31) continue;
#pragma unroll
            for (int kx = 0; kx < 3; kx++) {
                int xx = x + kx - 1;
                if (xx < 0 || xx > 31) continue;
                float4 k4 = *(const float4*)&k2s[(yy * 32 + xx) * 4];
                int j = ky * 3 + kx;
                acc[0][j] += k4.x * e4.x;
                acc[1][j] += k4.y * e4.y;
                acc[2][j] += k4.z * e4.z;
                acc[3][j] += k4.w * e4.w;
            }
        }
    }
#pragma unroll
    for (int dl = 0; dl < 4; dl++)
#pragma unroll
        for (int j = 0; j < 9; j++) {
            float v = acc[dl][j];
#pragma unroll
            for (int o = 16; o > 0; o >>= 1) v += __shfl_down_sync(0xffffffffu, v, o);
            if (lane == 0) atomicAdd(&gsum[dl * 9 + j], v);
        }
    __syncthreads();
    if (tid < 4) {
        float nrm = 0.f;
#pragma unroll
        for (int j = 0; j < 9; j++) nrm += gsum[tid * 9 + j] * gsum[tid * 9 + j];
        float inv = 1.f / (sqrtf(nrm) + 1.f);
#pragma unroll
        for (int j = 0; j < 9; j++)
            w3s[tid * 9 + j] = w3[(d0c + tid) * 9 + j] - gsum[tid * 9 + j] * inv;
    }
    __syncthreads();

#pragma unroll
    for (int it = 0; it < 4; it++) {
        int p = tid + it * 256;
        int y = p >> 5, x = p & 31;
        float4 a = make_float4(0.f, 0.f, 0.f, 0.f);
#pragma unroll
        for (int ky = 0; ky < 3; ky++) {
            int yy = y + ky - 1;
            if (yy < 0 || yy > 31) continue;
#pragma unroll
            for (int kx = 0; kx < 3; kx++) {
                int xx = x + kx - 1;
                if (xx < 0 || xx > 31) continue;
                float4 q4 = *(const float4*)&q2s[(yy * 32 + xx) * 4];
                int j = ky * 3 + kx;
                a.x += q4.x * w3s[j];
                a.y += q4.y * w3s[9 + j];
                a.z += q4.z * w3s[18 + j];
                a.w += q4.w * w3s[27 + j];
            }
        }
        *(float4*)&g_xcat[(rowbase + p) * XCATC + CC + d0c] = a;
    }
}

__global__ __launch_bounds__(256, 2) void apply_dwc_kernel(const float* __restrict__ w3)
{
    extern __shared__ float ap[];
    if (blockIdx.x < BB * HH * 2)
        apply_x1_body(ap, blockIdx.x);
    else
        dwc_x2_body(ap, blockIdx.x - BB * HH * 2, w3);
}

// ---------------------------------------------------------------------------
// Launch (single stream — graph-capture safe)
// ---------------------------------------------------------------------------
extern "C" void kernel_launch(void* const* d_in, const int* in_sizes, int n_in,
                              void* d_out, int out_size)
{
    const float* x      = (const float*)d_in[0];
    const float* W_qkv  = (const float*)d_in[1];
    const float* b_qkv  = (const float*)d_in[2];
    const float* w1     = (const float*)d_in[3];
    const float* w2     = (const float*)d_in[4];
    const float* w3     = (const float*)d_in[5];
    const float* proj_W = (const float*)d_in[6];
    const float* proj_b = (const float*)d_in[7];
    float* out = (float*)d_out;

    float *qkv, *xcat, *Wt1, *Wt2;
    cudaGetSymbolAddress((void**)&qkv,  g_qkv);
    cudaGetSymbolAddress((void**)&xcat, g_xcat);
    cudaGetSymbolAddress((void**)&Wt1,  g_Wt1);
    cudaGetSymbolAddress((void**)&Wt2,  g_Wt2);

    const int SMEM_BYTES = 3 * STAGE_BYTES;  // 98304
    cudaFuncSetAttribute(gemm_mma_kernel, cudaFuncAttributeMaxDynamicSharedMemorySize, SMEM_BYTES);
    cudaFuncSetAttribute(swiglu_grad_kernel, cudaFuncAttributeMaxDynamicSharedMemorySize, SW_BYTES);
    cudaFuncSetAttribute(apply_dwc_kernel, cudaFuncAttributeMaxDynamicSharedMemorySize, AP_BYTES);

    // Transposes: Wt1[n][k] = W_qkv[k][n] (pad to 2560 rows); Wt2[n][k] = proj_W[k][n]
    {
        dim3 blk(32, 8);
        transpose_pad_kernel<<<dim3(2560 / 32, CC / 32), blk>>>(W_qkv, Wt1, CC, OUTF, 2560);
        transpose_pad_kernel<<<dim3(CC / 32, XCATC / 32), blk>>>(proj_W, Wt2, XCATC, CC, CC);
    }
    // GEMM1: qkv = x @ W_qkv + b_qkv   [32768,768] x [768,2496]
    {
        dim3 grid(2560 / NT, MROWS / MT);
        gemm_mma_kernel<<<grid, 128, SMEM_BYTES>>>(x, Wt1, b_qkv, qkv, MROWS, OUTF, CC);
    }
    // SwiGLU gradient + weight update (V staged in smem, conflict-free E layout)
    swiglu_grad_kernel<<<BB * HH, 512, SW_BYTES>>>(w1, w2);
    // Fused x1 apply + dwc (dwc blocks fill apply's tail waves)
    apply_dwc_kernel<<<BB * HH * 2 + BB * 16, 256, AP_BYTES>>>(w3);
    // GEMM2: out = xcat @ proj_W + proj_b   [32768,832] x [832,768]
    {
        dim3 grid(CC / NT, MROWS / MT);
        gemm_mma_kernel<<<grid, 128, SMEM_BYTES>>>(xcat, Wt2, proj_b, out, MROWS, CC, XCATC);
    }
}